// round 14
// baseline (speedup 1.0000x reference)
#include <cuda_runtime.h>

#define Bb   8
#define Nn   8192
#define Mm   2048
#define Cc   64
#define CTt  64
#define KNN  32
#define TILE 512
#define SP2  68    // floats per staged row-half; 272B, 16B-aligned

// Scratch (__device__ globals; cudaMalloc is forbidden)
__device__ float  g_comb[(size_t)Bb * Nn * 128];   // 32 MB [b][n][feat|temb]
__device__ float4 g_xyz[(size_t)Bb * Nn];          //  4 MB  (x,y,z,|p|^2)
__device__ int    g_idx[Bb * Mm * KNN];            //  2 MB

__device__ __forceinline__ void cp16(void* sdst, const void* gsrc) {
    unsigned sa = (unsigned)__cvta_generic_to_shared(sdst);
    asm volatile("cp.async.cg.shared.global [%0], [%1], 16;"
                 :: "r"(sa), "l"(gsrc));
}
#define CP_COMMIT() asm volatile("cp.async.commit_group;")
#define CP_WAIT1()  asm volatile("cp.async.wait_group 1;")
#define CP_WAIT0()  asm volatile("cp.async.wait_group 0;")

// ---------------------------------------------------------------------------
// xyz packing (main stream, ahead of scan)
// ---------------------------------------------------------------------------
__global__ void xyz_kernel(const float* __restrict__ pts)   // [B][3][N]
{
    int g = blockIdx.x * blockDim.x + threadIdx.x;
    int b = g >> 13;
    int n = g & (Nn - 1);
    const float* p = pts + (size_t)b * 3 * Nn;
    float x = p[n], y = p[Nn + n], z = p[2 * Nn + n];
    float pn = __fadd_rn(__fadd_rn(__fmul_rn(x, x), __fmul_rn(y, y)),
                         __fmul_rn(z, z));
    g_xyz[g] = make_float4(x, y, z, pn);
}

// ---------------------------------------------------------------------------
// Prep (side stream): transpose [B][C][N] -> combined [B][N][128]
// ---------------------------------------------------------------------------
__global__ void prep_kernel(const float* __restrict__ feat,
                            const float* __restrict__ temb)
{
    __shared__ float tile[32][33];
    int zz    = blockIdx.z;
    int b     = zz >> 1;
    int which = zz & 1;
    const float* src = which ? temb : feat;
    int cbase        = which ? 64 : 0;

    int n0 = blockIdx.x * 32;
    int c0 = blockIdx.y * 32;
    int j  = threadIdx.x;                     // 0..7
    int i  = threadIdx.y;                     // 0..31

    const float* s = src + (size_t)b * Cc * Nn;
    float*       d = g_comb + (size_t)b * Nn * 128;

    float4 v = __ldcs((const float4*)(s + (size_t)(c0 + i) * Nn + n0 + 4 * j));
    tile[i][4 * j + 0] = v.x;
    tile[i][4 * j + 1] = v.y;
    tile[i][4 * j + 2] = v.z;
    tile[i][4 * j + 3] = v.w;
    __syncthreads();

    float4 w;
    w.x = tile[4 * j + 0][i];
    w.y = tile[4 * j + 1][i];
    w.z = tile[4 * j + 2][i];
    w.w = tile[4 * j + 3][i];
    *(float4*)(d + (size_t)(n0 + i) * 128 + cbase + c0 + 4 * j) = w;
}

// ---------------------------------------------------------------------------
// Scan: ordered first-K ball query, 8 warps/CTA, shared double-buffered tiles
// ---------------------------------------------------------------------------
__global__ void __launch_bounds__(256)
scan_kernel(const float* __restrict__ ctr)     // [B][3][M]
{
    __shared__ __align__(16) float4 sbuf[2][TILE];   // 16KB
    __shared__ int sidx[8][KNN];

    int t    = threadIdx.x;
    int warp = t >> 5;
    int lane = t & 31;
    int gw   = blockIdx.x * 8 + warp;
    int b    = gw >> 11;
    int m    = gw & (Mm - 1);

    float cx = ctr[(size_t)b * 3 * Mm + m];
    float cy = ctr[(size_t)b * 3 * Mm + Mm + m];
    float cz = ctr[(size_t)b * 3 * Mm + 2 * Mm + m];
    float cn = __fadd_rn(__fadd_rn(__fmul_rn(cx, cx), __fmul_rn(cy, cy)),
                         __fmul_rn(cz, cz));

    const float4* xyz = g_xyz + (size_t)b * Nn;
    const float R2 = (float)(0.2 * 0.2);

#pragma unroll
    for (int q = 0; q < 2; q++)
        cp16(&sbuf[0][t + q * 256], xyz + t + q * 256);
    CP_COMMIT();

    int count = 0;
    for (int tt = 0; tt < Nn / TILE; tt++) {
        float4* spts = sbuf[tt & 1];
        float4* snxt = sbuf[(tt + 1) & 1];
        if (tt + 1 < Nn / TILE) {
#pragma unroll
            for (int q = 0; q < 2; q++)
                cp16(&snxt[t + q * 256], xyz + (tt + 1) * TILE + t + q * 256);
        }
        CP_COMMIT();
        CP_WAIT1();
        __syncthreads();

        if (count < KNN) {
            int t0 = tt * TILE;
            for (int g = 0; g < TILE && count < KNN; g += 128) {
                float4 p0 = spts[g + lane];
                float4 p1 = spts[g + 32 + lane];
                float4 p2 = spts[g + 64 + lane];
                float4 p3 = spts[g + 96 + lane];
#pragma unroll
                for (int i = 0; i < 4; i++) {
                    float4 p = (i == 0) ? p0 : (i == 1) ? p1
                             : (i == 2) ? p2 : p3;
                    float cross = fmaf(cz, p.z,
                                       fmaf(cy, p.y, __fmul_rn(cx, p.x)));
                    float d2 = __fsub_rn(__fadd_rn(cn, p.w),
                                         __fmul_rn(2.0f, cross));
                    bool valid = d2 < R2;
                    unsigned mask = __ballot_sync(0xffffffffu, valid);
                    if (valid) {
                        int pos = count + __popc(mask & ((1u << lane) - 1u));
                        if (pos < KNN)
                            sidx[warp][pos] = t0 + g + i * 32 + lane;
                    }
                    count += __popc(mask);
                }
            }
        }
        if (__syncthreads_and(count >= KNN)) break;
    }
    CP_WAIT0();
    __syncwarp();

    int cnt   = min(count, KNN);
    int first = (cnt > 0) ? sidx[warp][0] : 0;
    int n     = (lane < cnt) ? sidx[warp][lane] : first;
    g_idx[(size_t)gw * KNN + lane] = n;
}

// ---------------------------------------------------------------------------
// Emit: 16 cp.async-pipelined phases = 8 centers x {feat, temb} halves.
// Staging: granule g (=cc>>2) of row k at word 4*((g ^ (k>>2)) & 15) + (cc&3)
// ---------------------------------------------------------------------------
__global__ void __launch_bounds__(256)
emit_kernel(const float* __restrict__ ctr,     // [B][3][M]
            float* __restrict__ out1,          // [B][67][M][K]
            float* __restrict__ out2)          // [B][64][M][K]
{
    __shared__ __align__(16) float  stg[2][KNN * SP2];   // 17.0KB
    __shared__ __align__(16) float4 spc[KNN];
    __shared__ int    sidx[8][KNN];
    __shared__ float  scen[8][3];

    int t    = threadIdx.x;
    int warp = t >> 5;
    int lane = t & 31;
    int gw   = blockIdx.x * 8 + warp;
    int b    = gw >> 11;
    int m    = gw & (Mm - 1);

    ((int*)sidx)[t] = g_idx[(size_t)blockIdx.x * 256 + t];
    if (lane < 3)
        scen[warp][lane] = ctr[(size_t)b * 3 * Mm + lane * Mm + m];
    __syncthreads();

    const size_t cs = (size_t)Mm * KNN;
    const float4* combB = (const float4*)g_comb + (size_t)b * Nn * 32;
    int t7 = lane & 7;         // k-quad 0..7
    int u  = lane >> 3;        // channel-within-quad 0..3
    int gB = lane & 15;        // granule within row-half
    int rH = lane >> 4;        // row-pair selector

#define STAGE_P(p)                                                           \
    {                                                                        \
        int ci_ = (p) >> 1, hf_ = (p) & 1;                                   \
        _Pragma("unroll")                                                    \
        for (int q = 0; q < 2; q++) {                                        \
            int r  = warp + 8 * (2 * q + rH);                                \
            int nk = sidx[ci_][r];                                           \
            cp16(&stg[hf_][r * SP2 + 4 * ((gB ^ (r >> 2)) & 15)],            \
                 combB + (size_t)nk * 32 + hf_ * 16 + gB);                   \
        }                                                                    \
        if (hf_ == 0 && lane < 4) {                                          \
            int r = warp + lane * 8;                                         \
            cp16(&spc[r], &g_xyz[(size_t)b * Nn + sidx[ci_][r]]);            \
        }                                                                    \
        CP_COMMIT();                                                         \
    }

    STAGE_P(0);
    for (int p = 0; p < 16; p++) {
        if (p < 15) STAGE_P(p + 1)
        else        CP_COMMIT();
        CP_WAIT1();
        __syncthreads();

        int ci = p >> 1, hf = p & 1;
        int mi = (blockIdx.x * 8 + ci) & (Mm - 1);
        float* o1 = out1 + ((size_t)b * 67 * Mm + mi) * KNN;
        float* o2 = out2 + ((size_t)b * 64 * Mm + mi) * KNN;

#pragma unroll
        for (int q = 0; q < 2; q++) {
            int Qp = warp + 8 * q;             // local quad 0..15
            int sb = 4 * ((Qp ^ t7) & 15) + u;
            float4 o;
            o.x = stg[hf][(4 * t7 + 0) * SP2 + sb];
            o.y = stg[hf][(4 * t7 + 1) * SP2 + sb];
            o.z = stg[hf][(4 * t7 + 2) * SP2 + sb];
            o.w = stg[hf][(4 * t7 + 3) * SP2 + sb];
            int ccl = 4 * Qp + u;              // local channel 0..63
            float* dst = hf ? (o2 + (size_t)ccl * cs)
                            : (o1 + (size_t)(3 + ccl) * cs);
            __stcs((float4*)(dst + 4 * t7), o);
        }
        if (hf == 0 && warp < 3) {
            float4 pv = spc[lane];
            float comp = (warp == 0) ? pv.x : (warp == 1) ? pv.y : pv.z;
            __stcs(&o1[(size_t)warp * cs + lane],
                   __fsub_rn(comp, scen[ci][warp]));
        }
        __syncthreads();
    }
#undef STAGE_P
}

// ---------------------------------------------------------------------------
extern "C" void kernel_launch(void* const* d_in, const int* in_sizes, int n_in,
                              void* d_out, int out_size)
{
    const float* pts  = (const float*)d_in[0];   // points_coords  [B,3,N]
    const float* ctr  = (const float*)d_in[1];   // centers_coords [B,3,M]
    const float* temb = (const float*)d_in[2];   // temb           [B,CT,N]
    const float* feat = (const float*)d_in[3];   // points_features[B,C,N]

    float* out1 = (float*)d_out;                                   // [B,67,M,K]
    float* out2 = out1 + (size_t)Bb * (3 + Cc) * Mm * KNN;         // [B,64,M,K]

    // One-time side-stream / event creation (host-side resources only).
    static cudaStream_t s2 = nullptr;
    static cudaEvent_t  evA = nullptr, evB = nullptr;
    if (!s2) {
        cudaStreamCreateWithFlags(&s2, cudaStreamNonBlocking);
        cudaEventCreateWithFlags(&evA, cudaEventDisableTiming);
        cudaEventCreateWithFlags(&evB, cudaEventDisableTiming);
    }

    // Fork: prep (transpose) runs on s2 concurrently with xyz+scan.
    cudaEventRecord(evA, 0);
    cudaStreamWaitEvent(s2, evA, 0);
    {
        dim3 tb(8, 32);
        dim3 tg(Nn / 32, Cc / 32, Bb * 2);
        prep_kernel<<<tg, tb, 0, s2>>>(feat, temb);
    }
    cudaEventRecord(evB, s2);

    xyz_kernel<<<(Bb * Nn) / 256, 256>>>(pts);
    scan_kernel<<<(Bb * Mm) / 8, 256>>>(ctr);

    // Join: emit needs both scan (main stream) and prep (s2).
    cudaStreamWaitEvent(0, evB, 0);
    emit_kernel<<<(Bb * Mm) / 8, 256>>>(ctr, out1, out2);
}

// round 15
// speedup vs baseline: 1.1959x; 1.1959x over previous
#include <cuda_runtime.h>

#define Bb   8
#define Nn   8192
#define Mm   2048
#define Cc   64
#define CTt  64
#define KNN  32
#define TILE 1024
#define SPITCH 132   // floats; 528B rows, 16B-aligned for 16B async copies

// Scratch (__device__ globals; cudaMalloc is forbidden)
// g_comb row n: [feat c0..63 | temb c0..63]
__device__ float  g_comb[(size_t)Bb * Nn * 128];   // 32 MB (L2-resident)
__device__ float4 g_xyz[(size_t)Bb * Nn];          //  4 MB  (x,y,z,|p|^2)

__device__ __forceinline__ void cp16(void* sdst, const void* gsrc) {
    unsigned sa = (unsigned)__cvta_generic_to_shared(sdst);
    asm volatile("cp.async.cg.shared.global [%0], [%1], 16;"
                 :: "r"(sa), "l"(gsrc));
}
#define CP_COMMIT() asm volatile("cp.async.commit_group;")
#define CP_WAIT1()  asm volatile("cp.async.wait_group 1;")
#define CP_WAIT0()  asm volatile("cp.async.wait_group 0;")

// ---------------------------------------------------------------------------
// Prep: transpose [B][C][N] -> combined [B][N][128], plus xyz packing.
// ILP 2: each thread moves 2 float4 rows.  block (8,32); grid (Nn/32,1,B*2)
// ---------------------------------------------------------------------------
__global__ void prep_kernel(const float* __restrict__ feat,
                            const float* __restrict__ temb,
                            const float* __restrict__ pts)
{
    __shared__ float tile[2][32][33];
    int zz    = blockIdx.z;
    int b     = zz >> 1;
    int which = zz & 1;
    const float* src = which ? temb : feat;
    int cbase        = which ? 64 : 0;

    int n0 = blockIdx.x * 32;
    int j  = threadIdx.x;                     // 0..7
    int i  = threadIdx.y;                     // 0..31
    int t  = i * 8 + j;

    const float* s = src + (size_t)b * Cc * Nn;
    float*       d = g_comb + (size_t)b * Nn * 128;

    float4 v0 = __ldcs((const float4*)(s + (size_t)i * Nn + n0 + 4 * j));
    float4 v1 = __ldcs((const float4*)(s + (size_t)(i + 32) * Nn + n0 + 4 * j));
    tile[0][i][4*j+0] = v0.x; tile[0][i][4*j+1] = v0.y;
    tile[0][i][4*j+2] = v0.z; tile[0][i][4*j+3] = v0.w;
    tile[1][i][4*j+0] = v1.x; tile[1][i][4*j+1] = v1.y;
    tile[1][i][4*j+2] = v1.z; tile[1][i][4*j+3] = v1.w;

    if (which == 0 && t < 32) {
        int n = n0 + t;
        const float* p = pts + (size_t)b * 3 * Nn;
        float x = p[n], y = p[Nn + n], z = p[2 * Nn + n];
        float pn = __fadd_rn(__fadd_rn(__fmul_rn(x, x), __fmul_rn(y, y)),
                             __fmul_rn(z, z));
        g_xyz[(size_t)b * Nn + n] = make_float4(x, y, z, pn);
    }
    __syncthreads();

    float4 w0, w1;
    w0.x = tile[0][4*j+0][i]; w0.y = tile[0][4*j+1][i];
    w0.z = tile[0][4*j+2][i]; w0.w = tile[0][4*j+3][i];
    w1.x = tile[1][4*j+0][i]; w1.y = tile[1][4*j+1][i];
    w1.z = tile[1][4*j+2][i]; w1.w = tile[1][4*j+3][i];
    float* row = d + (size_t)(n0 + i) * 128 + cbase;
    *(float4*)(row + 4 * j)      = w0;
    *(float4*)(row + 32 + 4 * j) = w1;
}

// ---------------------------------------------------------------------------
// Fused ball-query + gather + emit (R12 structure).  8 warps/CTA.
// Scan: batched 4-ballot rounds.  Emit: cp.async center ping-pong.
// Staging layout: channel cc of neighbor k at
//      stg[k*SPITCH + 4*((cc>>2)^(k>>2)) + (cc&3)]
// ---------------------------------------------------------------------------
__global__ void __launch_bounds__(256)
fused_kernel(const float* __restrict__ ctr,    // [B][3][M]
             float* __restrict__ out1,         // [B][67][M][K]
             float* __restrict__ out2)         // [B][64][M][K]
{
    __shared__ __align__(16) float  stg[2][KNN * SPITCH];  // 33.8KB dual-use
    __shared__ __align__(16) float4 spc[2][KNN];           // 1KB
    __shared__ int    sidx[8][KNN];
    __shared__ float  scen[8][3];

    int t    = threadIdx.x;
    int warp = t >> 5;
    int lane = t & 31;
    int gw   = blockIdx.x * 8 + warp;
    int b    = gw >> 11;                  // same b for all 8 centers of a CTA
    int m    = gw & (Mm - 1);

    float cx = ctr[(size_t)b * 3 * Mm + m];
    float cy = ctr[(size_t)b * 3 * Mm + Mm + m];
    float cz = ctr[(size_t)b * 3 * Mm + 2 * Mm + m];
    float cn = __fadd_rn(__fadd_rn(__fmul_rn(cx, cx), __fmul_rn(cy, cy)),
                         __fmul_rn(cz, cz));
    if (lane == 0) {
        scen[warp][0] = cx; scen[warp][1] = cy; scen[warp][2] = cz;
    }

    const float4* xyz = g_xyz + (size_t)b * Nn;
    const float R2 = (float)(0.2 * 0.2);
    const unsigned lt = (1u << lane) - 1u;

    // ---- ordered first-K scan, double-buffered tile prefetch ----
    float4* sbuf0 = (float4*)stg[0];
    float4* sbuf1 = (float4*)stg[1];

#pragma unroll
    for (int q = 0; q < 4; q++)                  // prefetch tile 0
        cp16(&sbuf0[t + q * 256], xyz + t + q * 256);
    CP_COMMIT();

    int count = 0;
    for (int tt = 0; tt < Nn / TILE; tt++) {
        float4* spts = (tt & 1) ? sbuf1 : sbuf0;
        float4* snxt = (tt & 1) ? sbuf0 : sbuf1;
        if (tt + 1 < Nn / TILE) {
#pragma unroll
            for (int q = 0; q < 4; q++)
                cp16(&snxt[t + q * 256],
                     xyz + (tt + 1) * TILE + t + q * 256);
        }
        CP_COMMIT();
        CP_WAIT1();                    // current tile's copies done
        __syncthreads();

        if (count < KNN) {
            int t0 = tt * TILE;
            for (int g = 0; g < TILE && count < KNN; g += 128) {
                float4 p0 = spts[g + lane];
                float4 p1 = spts[g + 32 + lane];
                float4 p2 = spts[g + 64 + lane];
                float4 p3 = spts[g + 96 + lane];

                float cr0 = fmaf(cz, p0.z, fmaf(cy, p0.y, __fmul_rn(cx, p0.x)));
                float cr1 = fmaf(cz, p1.z, fmaf(cy, p1.y, __fmul_rn(cx, p1.x)));
                float cr2 = fmaf(cz, p2.z, fmaf(cy, p2.y, __fmul_rn(cx, p2.x)));
                float cr3 = fmaf(cz, p3.z, fmaf(cy, p3.y, __fmul_rn(cx, p3.x)));
                float d0 = __fsub_rn(__fadd_rn(cn, p0.w), __fmul_rn(2.0f, cr0));
                float d1 = __fsub_rn(__fadd_rn(cn, p1.w), __fmul_rn(2.0f, cr1));
                float d2 = __fsub_rn(__fadd_rn(cn, p2.w), __fmul_rn(2.0f, cr2));
                float d3 = __fsub_rn(__fadd_rn(cn, p3.w), __fmul_rn(2.0f, cr3));
                bool v0 = d0 < R2, v1 = d1 < R2, v2 = d2 < R2, v3 = d3 < R2;

                unsigned m0 = __ballot_sync(0xffffffffu, v0);
                unsigned m1 = __ballot_sync(0xffffffffu, v1);
                unsigned m2 = __ballot_sync(0xffffffffu, v2);
                unsigned m3 = __ballot_sync(0xffffffffu, v3);

                int c0 = count;
                int c1 = c0 + __popc(m0);
                int c2 = c1 + __popc(m1);
                int c3 = c2 + __popc(m2);
                if (v0) { int pos = c0 + __popc(m0 & lt);
                          if (pos < KNN) sidx[warp][pos] = t0 + g + lane; }
                if (v1) { int pos = c1 + __popc(m1 & lt);
                          if (pos < KNN) sidx[warp][pos] = t0 + g + 32 + lane; }
                if (v2) { int pos = c2 + __popc(m2 & lt);
                          if (pos < KNN) sidx[warp][pos] = t0 + g + 64 + lane; }
                if (v3) { int pos = c3 + __popc(m3 & lt);
                          if (pos < KNN) sidx[warp][pos] = t0 + g + 96 + lane; }
                count = c3 + __popc(m3);
            }
        }
        if (__syncthreads_and(count >= KNN)) break;
    }
    CP_WAIT0();                        // drain stale prefetches
    __syncwarp();

    // finalize index list (fill tail with first valid / 0)
    int cnt   = min(count, KNN);
    int first = (cnt > 0) ? sidx[warp][0] : 0;
    int n     = (lane < cnt) ? sidx[warp][lane] : first;
    __syncwarp();
    sidx[warp][lane] = n;
    __syncthreads();                   // sidx complete, buffers reusable

    // ---- emit pipeline: stage center i+1 while emitting center i ----
    const size_t cs = (size_t)Mm * KNN;
    const float4* combB = (const float4*)g_comb + (size_t)b * Nn * 32;
    int t7 = lane & 7;         // k-quad 0..7
    int u  = lane >> 3;        // channel-within-quad 0..3

#define STAGE(ci, bf)                                                        \
    {                                                                        \
        _Pragma("unroll")                                                    \
        for (int q = 0; q < 4; q++) {                                        \
            int r  = warp + q * 8;                                           \
            int nk = sidx[ci][r];                                            \
            cp16(&stg[bf][r * SPITCH + 4 * (lane ^ (r >> 2))],               \
                 combB + (size_t)nk * 32 + lane);                            \
        }                                                                    \
        if (lane < 4) {                                                      \
            int r = warp + lane * 8;                                         \
            cp16(&spc[bf][r], &g_xyz[(size_t)b * Nn + sidx[ci][r]]);         \
        }                                                                    \
        CP_COMMIT();                                                         \
    }

    STAGE(0, 0);
    for (int i = 0; i < 8; i++) {
        int bf = i & 1;
        if (i < 7) STAGE(i + 1, (i + 1) & 1)
        else       CP_COMMIT();
        CP_WAIT1();                    // center i's copies done
        __syncthreads();

        int mi = (blockIdx.x * 8 + i) & (Mm - 1);
        float* o1 = out1 + ((size_t)b * 67 * Mm + mi) * KNN;
        float* o2 = out2 + ((size_t)b * 64 * Mm + mi) * KNN;

        // 32 channel-quads; warp w handles Q = w, w+8, w+16, w+24.
#pragma unroll
        for (int q = 0; q < 4; q++) {
            int Q  = warp + 8 * q;
            int cc = 4 * Q + u;
            int sb = 4 * (Q ^ t7) + u;
            float4 o;
            o.x = stg[bf][(4 * t7 + 0) * SPITCH + sb];
            o.y = stg[bf][(4 * t7 + 1) * SPITCH + sb];
            o.z = stg[bf][(4 * t7 + 2) * SPITCH + sb];
            o.w = stg[bf][(4 * t7 + 3) * SPITCH + sb];
            float* dst = (cc < 64) ? (o1 + (size_t)(3 + cc) * cs)
                                   : (o2 + (size_t)(cc - 64) * cs);
            __stcs((float4*)(dst + 4 * t7), o);
        }
        // coord channels 0..2: warps 0..2, one 128B line each
        if (warp < 3) {
            float4 pv = spc[bf][lane];
            float comp = (warp == 0) ? pv.x : (warp == 1) ? pv.y : pv.z;
            __stcs(&o1[(size_t)warp * cs + lane],
                   __fsub_rn(comp, scen[i][warp]));
        }
        __syncthreads();   // emit(i) done before buffer bf is restaged
    }
#undef STAGE
}

// ---------------------------------------------------------------------------
extern "C" void kernel_launch(void* const* d_in, const int* in_sizes, int n_in,
                              void* d_out, int out_size)
{
    const float* pts  = (const float*)d_in[0];   // points_coords  [B,3,N]
    const float* ctr  = (const float*)d_in[1];   // centers_coords [B,3,M]
    const float* temb = (const float*)d_in[2];   // temb           [B,CT,N]
    const float* feat = (const float*)d_in[3];   // points_features[B,C,N]

    float* out1 = (float*)d_out;                                   // [B,67,M,K]
    float* out2 = out1 + (size_t)Bb * (3 + Cc) * Mm * KNN;         // [B,64,M,K]

    dim3 tb(8, 32);
    dim3 tg(Nn / 32, 1, Bb * 2);
    prep_kernel<<<tg, tb>>>(feat, temb, pts);

    fused_kernel<<<(Bb * Mm) / 8, 256>>>(ctr, out1, out2);
}